// round 1
// baseline (speedup 1.0000x reference)
#include <cuda_runtime.h>
#include <math.h>
#include <float.h>

#define NB    64
#define NGPB  2000
#define EGPB  64000
#define NN    (NB*NGPB)     // 128000 nodes
#define NE    (NB*EGPB)     // 4096000 edges
#define KSEL  1600
#define EMB   64
#define G1    32
#define G2    32
#define DENSE 64
#define NCLS  10
#define FEAT  10000

// ---------------- scratch (static device globals; no runtime alloc) ----------
__device__ int   g_deg[NN];
__device__ int   g_start[NN];
__device__ int   g_cursor[NN];
__device__ float g_dinv[NN];
__device__ int   g_csrc[NE];          // CSR: incoming src per dst
__device__ float g_embW1[FEAT*G1];    // emb @ W1  (10000 x 32)
__device__ float g_hs [NN*G1];        // layer-1 input, pre-scaled by dinv[src]
__device__ float g_hs2[NN*G2];        // layer-2 input, pre-scaled by dinv[src]
__device__ float g_h2 [NN*G2];        // final node features
__device__ float g_score[NN];

// ---------------- degree count ----------------------------------------------
__global__ void k_zero_deg() {
    int i = blockIdx.x*blockDim.x + threadIdx.x;
    if (i < NN) g_deg[i] = 0;
}

__global__ void k_count(const int* __restrict__ ei) {
    int i = blockIdx.x*blockDim.x + threadIdx.x;
    if (i < NE) atomicAdd(&g_deg[ei[NE + i]], 1);   // ei[1] = dst
}

// per-batch prefix scan of degrees -> CSR offsets, cursors, dinv
__global__ void k_scan() {
    __shared__ int sa[2048], sb[2048];
    int b = blockIdx.x, tid = threadIdx.x;
    for (int i = tid; i < 2048; i += 1024)
        sa[i] = (i < NGPB) ? g_deg[b*NGPB + i] : 0;
    __syncthreads();
    int *src = sa, *dst = sb;
    for (int off = 1; off < 2048; off <<= 1) {
        for (int i = tid; i < 2048; i += 1024)
            dst[i] = src[i] + (i >= off ? src[i-off] : 0);
        __syncthreads();
        int* t = src; src = dst; dst = t;
    }
    for (int i = tid; i < NGPB; i += 1024) {
        int v  = b*NGPB + i;
        int d  = g_deg[v];
        int st = b*EGPB + src[i] - d;          // exclusive prefix + batch base
        g_start[v]  = st;
        g_cursor[v] = st;
        g_dinv[v]   = rsqrtf((float)(d + 1));  // +1 self loop
    }
}

__global__ void k_scatter(const int* __restrict__ ei) {
    int i = blockIdx.x*blockDim.x + threadIdx.x;
    if (i < NE) {
        int s = ei[i];
        int d = ei[NE + i];
        int pos = atomicAdd(&g_cursor[d], 1);
        g_csrc[pos] = s;
    }
}

// ---------------- emb @ W1 (tiny table GEMM) ---------------------------------
__global__ void k_embW1(const float* __restrict__ emb, const float* __restrict__ W1) {
    __shared__ float W1s[EMB*G1];
    for (int i = threadIdx.x; i < EMB*G1; i += blockDim.x) W1s[i] = W1[i];
    __syncthreads();
    int warp = threadIdx.x >> 5, lane = threadIdx.x & 31;
    int r = blockIdx.x*8 + warp;
    if (r >= FEAT) return;
    float e0 = emb[r*EMB + lane];
    float e1 = emb[r*EMB + 32 + lane];
    float acc = 0.f;
    #pragma unroll
    for (int k = 0; k < 32; k++)
        acc += __shfl_sync(0xffffffffu, e0, k) * W1s[k*G1 + lane];
    #pragma unroll
    for (int k = 0; k < 32; k++)
        acc += __shfl_sync(0xffffffffu, e1, k) * W1s[(32+k)*G1 + lane];
    g_embW1[r*G1 + lane] = acc;
}

// hs[v] = (emb@W1)[x[v]] * dinv[v]
__global__ void k_hs(const int* __restrict__ x) {
    int i = blockIdx.x*blockDim.x + threadIdx.x;
    if (i >= NN*G1) return;
    int v = i >> 5, f = i & 31;
    g_hs[i] = g_embW1[x[v]*G1 + f] * g_dinv[v];
}

// ---------------- GCN aggregation (warp per dst node) ------------------------
// out[v] = relu(dinv[v] * (hs[v] + sum_{u->v} hs[u]) + bias)
// MODE 1: then fuse h1@W2, scale by dinv -> g_hs2
// MODE 2: write h2, compute tanh pooling score
template<int MODE>
__global__ void k_agg(const float* __restrict__ bias,
                      const float* __restrict__ W2,
                      const float* __restrict__ pw) {
    __shared__ float W2s[G2*G2];
    if (MODE == 1) {
        for (int i = threadIdx.x; i < G2*G2; i += blockDim.x) W2s[i] = W2[i];
        __syncthreads();
    }
    const float* __restrict__ gin = (MODE == 1) ? g_hs : g_hs2;
    int warp = threadIdx.x >> 5, lane = threadIdx.x & 31;
    int v = blockIdx.x*(blockDim.x >> 5) + warp;
    if (v >= NN) return;
    int st = g_start[v], dg = g_deg[v];
    float dinv = g_dinv[v];
    float a0 = gin[v*32 + lane], a1 = 0.f, a2 = 0.f, a3 = 0.f;  // self loop
    for (int base = 0; base < dg; base += 32) {
        int m = min(32, dg - base);
        int idx = (base + lane < dg) ? g_csrc[st + base + lane] : 0;
        int j = 0;
        for (; j + 4 <= m; j += 4) {
            int s0 = __shfl_sync(0xffffffffu, idx, j);
            int s1 = __shfl_sync(0xffffffffu, idx, j+1);
            int s2 = __shfl_sync(0xffffffffu, idx, j+2);
            int s3 = __shfl_sync(0xffffffffu, idx, j+3);
            a0 += gin[s0*32 + lane];
            a1 += gin[s1*32 + lane];
            a2 += gin[s2*32 + lane];
            a3 += gin[s3*32 + lane];
        }
        for (; j < m; j++) {
            int s = __shfl_sync(0xffffffffu, idx, j);
            a0 += gin[s*32 + lane];
        }
    }
    float val = fmaxf(dinv*((a0+a1)+(a2+a3)) + bias[lane], 0.f);
    if (MODE == 1) {
        float acc = 0.f;
        #pragma unroll
        for (int k = 0; k < 32; k++)
            acc += __shfl_sync(0xffffffffu, val, k) * W2s[k*G2 + lane];
        g_hs2[v*32 + lane] = acc * dinv;
    } else {
        g_h2[v*32 + lane] = val;
        float p   = pw[lane];
        float nrm = p*p;
        float dot = val*p;
        #pragma unroll
        for (int o = 16; o; o >>= 1) {
            nrm += __shfl_xor_sync(0xffffffffu, nrm, o);
            dot += __shfl_xor_sync(0xffffffffu, dot, o);
        }
        if (lane == 0) g_score[v] = tanhf(dot * rsqrtf(nrm));
    }
}

// ---------------- top-k pool + dense head (one CTA per batch) ----------------
__global__ void k_topk(const float* __restrict__ dense_W, const float* __restrict__ dense_b,
                       const float* __restrict__ out_W,  const float* __restrict__ out_b,
                       float* __restrict__ out) {
    __shared__ float ss[2048];
    __shared__ float red[32*32];
    __shared__ float gvec[G2];
    __shared__ float dvec[DENSE];
    int b = blockIdx.x, tid = threadIdx.x;
    for (int i = tid; i < 2048; i += 1024)
        ss[i] = (i < NGPB) ? g_score[b*NGPB + i] : -FLT_MAX;
    __syncthreads();
    // bitonic ascending sort of 2048 elements
    for (int k = 2; k <= 2048; k <<= 1)
        for (int j = k >> 1; j > 0; j >>= 1) {
            for (int i = tid; i < 2048; i += 1024) {
                int ixj = i ^ j;
                if (ixj > i) {
                    float a = ss[i], c = ss[ixj];
                    bool up = ((i & k) == 0);
                    if ((a > c) == up) { ss[i] = c; ss[ixj] = a; }
                }
            }
            __syncthreads();
        }
    float thr = ss[2048 - KSEL];   // K-th largest score
    // feature-wise max over selected nodes of h2[i]*score[i]
    int warp = tid >> 5, lane = tid & 31;
    float m = -FLT_MAX;
    for (int i = warp; i < NGPB; i += 32) {
        int v = b*NGPB + i;
        float sc = g_score[v];
        if (sc >= thr) m = fmaxf(m, g_h2[v*32 + lane] * sc);
    }
    red[warp*32 + lane] = m;
    __syncthreads();
    if (tid < G2) {
        float mm = -FLT_MAX;
        #pragma unroll
        for (int w = 0; w < 32; w++) mm = fmaxf(mm, red[w*32 + tid]);
        gvec[tid] = mm;
    }
    __syncthreads();
    if (tid < DENSE) {
        float acc = dense_b[tid];
        #pragma unroll
        for (int k = 0; k < G2; k++) acc += gvec[k]*dense_W[k*DENSE + tid];
        dvec[tid] = fmaxf(acc, 0.f);
    }
    __syncthreads();
    if (tid < NCLS) {
        float acc = out_b[tid];
        #pragma unroll
        for (int k = 0; k < DENSE; k++) acc += dvec[k]*out_W[k*NCLS + tid];
        out[b*NCLS + tid] = acc;
    }
}

// ---------------- launch -----------------------------------------------------
extern "C" void kernel_launch(void* const* d_in, const int* in_sizes, int n_in,
                              void* d_out, int out_size) {
    const int*   x   = (const int*)  d_in[0];
    const int*   ei  = (const int*)  d_in[1];
    // d_in[2] = batch (implicit in layout, unused)
    const float* emb = (const float*)d_in[3];
    const float* W1  = (const float*)d_in[4];
    const float* b1  = (const float*)d_in[5];
    const float* W2  = (const float*)d_in[6];
    const float* b2  = (const float*)d_in[7];
    const float* pw  = (const float*)d_in[8];
    const float* dW  = (const float*)d_in[9];
    const float* db  = (const float*)d_in[10];
    const float* oW  = (const float*)d_in[11];
    const float* ob  = (const float*)d_in[12];
    float* out = (float*)d_out;

    k_zero_deg<<<(NN + 255)/256, 256>>>();
    k_count   <<<(NE + 255)/256, 256>>>(ei);
    k_scan    <<<NB, 1024>>>();
    k_scatter <<<(NE + 255)/256, 256>>>(ei);
    k_embW1   <<<FEAT/8, 256>>>(emb, W1);
    k_hs      <<<(NN*G1 + 255)/256, 256>>>(x);
    k_agg<1>  <<<NN/8, 256>>>(b1, W2, pw);
    k_agg<2>  <<<NN/8, 256>>>(b2, W2, pw);
    k_topk    <<<NB, 1024>>>(dW, db, oW, ob, out);
}

// round 2
// speedup vs baseline: 1.5542x; 1.5542x over previous
#include <cuda_runtime.h>
#include <math.h>
#include <float.h>

#define NB    64
#define NGPB  2000
#define EGPB  64000
#define NN    (NB*NGPB)     // 128000 nodes
#define NE    (NB*EGPB)     // 4096000 edges
#define KSEL  1600
#define EMB   64
#define G1    32
#define G2    32
#define DENSE 64
#define NCLS  10
#define FEAT  10000
#define CAP   96            // padded CSR bucket capacity (deg mean 32, max ~62)

// ---------------- scratch (static device globals; no runtime alloc) ----------
__device__ int   g_cnt[NN];           // per-node in-degree / bucket cursor
__device__ float g_dinv[NN];
__device__ int   g_csrc[NN*CAP];      // padded CSR: incoming src per dst
__device__ float g_embW1[FEAT*G1];    // emb @ W1  (10000 x 32)
__device__ float g_hs [NN*G1];        // layer-1 input, pre-scaled by dinv[src]
__device__ float g_hs2[NN*G2];        // layer-2 input, pre-scaled by dinv[src]
__device__ float g_h2 [NN*G2];        // final node features
__device__ float g_score[NN];

// ---------------- CSR build: zero cursors, then one atomic scatter pass ------
__global__ void k_zero_cnt() {
    int i = blockIdx.x*blockDim.x + threadIdx.x;
    if (i < NN) g_cnt[i] = 0;
}

__global__ void k_scatter(const int* __restrict__ ei) {
    int i = blockIdx.x*blockDim.x + threadIdx.x;
    if (i < NE) {
        int s = ei[i];          // ei[0] = src
        int d = ei[NE + i];     // ei[1] = dst
        int pos = atomicAdd(&g_cnt[d], 1);
        g_csrc[d*CAP + pos] = s;
    }
}

// ---------------- emb @ W1 (tiny table GEMM) ---------------------------------
__global__ void k_embW1(const float* __restrict__ emb, const float* __restrict__ W1) {
    __shared__ float W1s[EMB*G1];
    for (int i = threadIdx.x; i < EMB*G1; i += blockDim.x) W1s[i] = W1[i];
    __syncthreads();
    int warp = threadIdx.x >> 5, lane = threadIdx.x & 31;
    int r = blockIdx.x*8 + warp;
    if (r >= FEAT) return;
    float e0 = emb[r*EMB + lane];
    float e1 = emb[r*EMB + 32 + lane];
    float acc = 0.f;
    #pragma unroll
    for (int k = 0; k < 32; k++)
        acc += __shfl_sync(0xffffffffu, e0, k) * W1s[k*G1 + lane];
    #pragma unroll
    for (int k = 0; k < 32; k++)
        acc += __shfl_sync(0xffffffffu, e1, k) * W1s[(32+k)*G1 + lane];
    g_embW1[r*G1 + lane] = acc;
}

// hs[v] = (emb@W1)[x[v]] * dinv[v];  also materializes dinv from cnt
__global__ void k_hs(const int* __restrict__ x) {
    int i = blockIdx.x*blockDim.x + threadIdx.x;
    if (i >= NN*G1) return;
    int v = i >> 5, f = i & 31;
    float dinv = rsqrtf((float)(g_cnt[v] + 1));   // +1 self loop
    if (f == 0) g_dinv[v] = dinv;
    g_hs[i] = g_embW1[x[v]*G1 + f] * dinv;
}

// ---------------- GCN aggregation (warp per dst node) ------------------------
// out[v] = relu(dinv[v] * (hs[v] + sum_{u->v} hs[u]) + bias)
// MODE 1: then fuse h1@W2, scale by dinv -> g_hs2
// MODE 2: write h2, compute tanh pooling score
template<int MODE>
__global__ void k_agg(const float* __restrict__ bias,
                      const float* __restrict__ W2,
                      const float* __restrict__ pw) {
    __shared__ float W2s[G2*G2];
    if (MODE == 1) {
        for (int i = threadIdx.x; i < G2*G2; i += blockDim.x) W2s[i] = W2[i];
        __syncthreads();
    }
    const float* __restrict__ gin = (MODE == 1) ? g_hs : g_hs2;
    int warp = threadIdx.x >> 5, lane = threadIdx.x & 31;
    int v = blockIdx.x*(blockDim.x >> 5) + warp;
    if (v >= NN) return;
    int dg = g_cnt[v];
    const int* __restrict__ bucket = g_csrc + v*CAP;
    float dinv = g_dinv[v];
    float a0 = gin[v*32 + lane], a1 = 0.f, a2 = 0.f, a3 = 0.f;  // self loop
    for (int base = 0; base < dg; base += 32) {
        int m = min(32, dg - base);
        int idx = (base + lane < dg) ? __ldg(bucket + base + lane) : 0;
        int j = 0;
        for (; j + 4 <= m; j += 4) {
            int s0 = __shfl_sync(0xffffffffu, idx, j);
            int s1 = __shfl_sync(0xffffffffu, idx, j+1);
            int s2 = __shfl_sync(0xffffffffu, idx, j+2);
            int s3 = __shfl_sync(0xffffffffu, idx, j+3);
            a0 += __ldg(gin + s0*32 + lane);
            a1 += __ldg(gin + s1*32 + lane);
            a2 += __ldg(gin + s2*32 + lane);
            a3 += __ldg(gin + s3*32 + lane);
        }
        for (; j < m; j++) {
            int s = __shfl_sync(0xffffffffu, idx, j);
            a0 += __ldg(gin + s*32 + lane);
        }
    }
    float val = fmaxf(dinv*((a0+a1)+(a2+a3)) + bias[lane], 0.f);
    if (MODE == 1) {
        float acc = 0.f;
        #pragma unroll
        for (int k = 0; k < 32; k++)
            acc += __shfl_sync(0xffffffffu, val, k) * W2s[k*G2 + lane];
        g_hs2[v*32 + lane] = acc * dinv;
    } else {
        g_h2[v*32 + lane] = val;
        float p   = pw[lane];
        float nrm = p*p;
        float dot = val*p;
        #pragma unroll
        for (int o = 16; o; o >>= 1) {
            nrm += __shfl_xor_sync(0xffffffffu, nrm, o);
            dot += __shfl_xor_sync(0xffffffffu, dot, o);
        }
        if (lane == 0) g_score[v] = tanhf(dot * rsqrtf(nrm));
    }
}

// ---------------- top-k pool + dense head (one CTA per batch) ----------------
__global__ void k_topk(const float* __restrict__ dense_W, const float* __restrict__ dense_b,
                       const float* __restrict__ out_W,  const float* __restrict__ out_b,
                       float* __restrict__ out) {
    __shared__ float ss[2048];
    __shared__ float red[32*32];
    __shared__ float gvec[G2];
    __shared__ float dvec[DENSE];
    int b = blockIdx.x, tid = threadIdx.x;
    for (int i = tid; i < 2048; i += 1024)
        ss[i] = (i < NGPB) ? g_score[b*NGPB + i] : -FLT_MAX;
    __syncthreads();
    // bitonic ascending sort of 2048 elements
    for (int k = 2; k <= 2048; k <<= 1)
        for (int j = k >> 1; j > 0; j >>= 1) {
            for (int i = tid; i < 2048; i += 1024) {
                int ixj = i ^ j;
                if (ixj > i) {
                    float a = ss[i], c = ss[ixj];
                    bool up = ((i & k) == 0);
                    if ((a > c) == up) { ss[i] = c; ss[ixj] = a; }
                }
            }
            __syncthreads();
        }
    float thr = ss[2048 - KSEL];   // K-th largest score
    // feature-wise max over selected nodes of h2[i]*score[i]
    int warp = tid >> 5, lane = tid & 31;
    float m = -FLT_MAX;
    for (int i = warp; i < NGPB; i += 32) {
        int v = b*NGPB + i;
        float sc = g_score[v];
        if (sc >= thr) m = fmaxf(m, g_h2[v*32 + lane] * sc);
    }
    red[warp*32 + lane] = m;
    __syncthreads();
    if (tid < G2) {
        float mm = -FLT_MAX;
        #pragma unroll
        for (int w = 0; w < 32; w++) mm = fmaxf(mm, red[w*32 + tid]);
        gvec[tid] = mm;
    }
    __syncthreads();
    if (tid < DENSE) {
        float acc = dense_b[tid];
        #pragma unroll
        for (int k = 0; k < G2; k++) acc += gvec[k]*dense_W[k*DENSE + tid];
        dvec[tid] = fmaxf(acc, 0.f);
    }
    __syncthreads();
    if (tid < NCLS) {
        float acc = out_b[tid];
        #pragma unroll
        for (int k = 0; k < DENSE; k++) acc += dvec[k]*out_W[k*NCLS + tid];
        out[b*NCLS + tid] = acc;
    }
}

// ---------------- launch -----------------------------------------------------
extern "C" void kernel_launch(void* const* d_in, const int* in_sizes, int n_in,
                              void* d_out, int out_size) {
    const int*   x   = (const int*)  d_in[0];
    const int*   ei  = (const int*)  d_in[1];
    // d_in[2] = batch (implicit in layout, unused)
    const float* emb = (const float*)d_in[3];
    const float* W1  = (const float*)d_in[4];
    const float* b1  = (const float*)d_in[5];
    const float* W2  = (const float*)d_in[6];
    const float* b2  = (const float*)d_in[7];
    const float* pw  = (const float*)d_in[8];
    const float* dW  = (const float*)d_in[9];
    const float* db  = (const float*)d_in[10];
    const float* oW  = (const float*)d_in[11];
    const float* ob  = (const float*)d_in[12];
    float* out = (float*)d_out;

    k_zero_cnt<<<(NN + 255)/256, 256>>>();
    k_scatter <<<(NE + 255)/256, 256>>>(ei);
    k_embW1   <<<FEAT/8, 256>>>(emb, W1);
    k_hs      <<<(NN*G1 + 511)/512, 512>>>(x);
    k_agg<1>  <<<NN/16, 512>>>(b1, W2, pw);
    k_agg<2>  <<<NN/16, 512>>>(b2, W2, pw);
    k_topk    <<<NB, 1024>>>(dW, db, oW, ob, out);
}

// round 3
// speedup vs baseline: 1.7408x; 1.1200x over previous
#include <cuda_runtime.h>
#include <math.h>
#include <float.h>

#define NB    64
#define NGPB  2000
#define EGPB  64000
#define NN    (NB*NGPB)     // 128000 nodes
#define NE    (NB*EGPB)     // 4096000 edges
#define KSEL  1600
#define EMB   64
#define G1    32
#define G2    32
#define DENSE 64
#define NCLS  10
#define FEAT  10000
#define CAP   96            // padded CSR bucket capacity (deg mean 32, max ~62)
#define HALF  1000          // dst nodes owned per build-CTA

// ---------------- scratch (static device globals; no runtime alloc) ----------
__device__ int   g_cnt[NN];           // per-node in-degree
__device__ float g_dinv[NN];
__device__ int   g_csrc[NN*CAP];      // padded CSR: incoming src per dst
__device__ float g_embW1[FEAT*G1];    // emb @ W1  (10000 x 32)
__device__ float g_hs [NN*G1];        // layer-1 input, pre-scaled by dinv[src]
__device__ float g_hs2[NN*G2];        // layer-2 input, pre-scaled by dinv[src]
__device__ float g_h2 [NN*G2];        // final node features
__device__ float g_score[NN];

// ---------------- emb @ W1 (tiny table GEMM) ---------------------------------
__global__ void k_embW1(const float* __restrict__ emb, const float* __restrict__ W1) {
    __shared__ float W1s[EMB*G1];
    for (int i = threadIdx.x; i < EMB*G1; i += blockDim.x) W1s[i] = W1[i];
    __syncthreads();
    int warp = threadIdx.x >> 5, lane = threadIdx.x & 31;
    int r = blockIdx.x*8 + warp;
    if (r >= FEAT) return;
    float e0 = emb[r*EMB + lane];
    float e1 = emb[r*EMB + 32 + lane];
    float acc = 0.f;
    #pragma unroll
    for (int k = 0; k < 32; k++)
        acc += __shfl_sync(0xffffffffu, e0, k) * W1s[k*G1 + lane];
    #pragma unroll
    for (int k = 0; k < 32; k++)
        acc += __shfl_sync(0xffffffffu, e1, k) * W1s[(32+k)*G1 + lane];
    g_embW1[r*G1 + lane] = acc;
}

// ---------------- fused CSR build + dinv + hs materialization ----------------
// 2 CTAs per batch; CTA owns dst range [b*NGPB + h*HALF, +HALF).
// Edges of batch b are contiguous in the edge list. SMEM atomics for cursors.
__global__ void __launch_bounds__(1024) k_build(const int* __restrict__ ei,
                                                const int* __restrict__ x) {
    __shared__ int scnt[HALF];
    int b = blockIdx.x >> 1, h = blockIdx.x & 1;
    int tid = threadIdx.x;
    for (int i = tid; i < HALF; i += 1024) scnt[i] = 0;
    __syncthreads();
    int ebase = b*EGPB;
    int lo    = b*NGPB + h*HALF;
    const int* __restrict__ srcs = ei + ebase;
    const int* __restrict__ dsts = ei + NE + ebase;
    for (int j = tid; j < EGPB; j += 1024) {
        int d = dsts[j];
        unsigned r = (unsigned)(d - lo);
        if (r < HALF) {
            int s = srcs[j];
            int pos = atomicAdd(&scnt[r], 1);
            g_csrc[d*CAP + pos] = s;
        }
    }
    __syncthreads();
    // cnt, dinv, hs for owned nodes (warp per node)
    int warp = tid >> 5, lane = tid & 31;
    for (int i = warp; i < HALF; i += 32) {
        int v = lo + i;
        int c = scnt[i];
        float dinv = rsqrtf((float)(c + 1));      // +1 self loop
        if (lane == 0) { g_cnt[v] = c; g_dinv[v] = dinv; }
        int row = x[v];
        g_hs[v*32 + lane] = g_embW1[row*32 + lane] * dinv;
    }
}

// ---------------- GCN aggregation (warp per dst node) ------------------------
// out[v] = relu(dinv[v] * (hs[v] + sum_{u->v} hs[u]) + bias)
// MODE 1: then fuse h1@W2, scale by dinv -> g_hs2
// MODE 2: write h2, compute tanh pooling score
template<int MODE>
__global__ void k_agg(const float* __restrict__ bias,
                      const float* __restrict__ W2,
                      const float* __restrict__ pw) {
    __shared__ float W2s[G2*G2];
    if (MODE == 1) {
        for (int i = threadIdx.x; i < G2*G2; i += blockDim.x) W2s[i] = W2[i];
        __syncthreads();
    }
    const float* __restrict__ gin = (MODE == 1) ? g_hs : g_hs2;
    int warp = threadIdx.x >> 5, lane = threadIdx.x & 31;
    int v = blockIdx.x*(blockDim.x >> 5) + warp;
    if (v >= NN) return;
    int dg = g_cnt[v];
    const int* __restrict__ bucket = g_csrc + v*CAP;
    float dinv = g_dinv[v];
    float a0 = gin[v*32 + lane], a1 = 0.f, a2 = 0.f, a3 = 0.f;  // self loop
    for (int base = 0; base < dg; base += 32) {
        int m = min(32, dg - base);
        int idx = (base + lane < dg) ? __ldg(bucket + base + lane) : 0;
        int j = 0;
        for (; j + 4 <= m; j += 4) {
            int s0 = __shfl_sync(0xffffffffu, idx, j);
            int s1 = __shfl_sync(0xffffffffu, idx, j+1);
            int s2 = __shfl_sync(0xffffffffu, idx, j+2);
            int s3 = __shfl_sync(0xffffffffu, idx, j+3);
            a0 += __ldg(gin + s0*32 + lane);
            a1 += __ldg(gin + s1*32 + lane);
            a2 += __ldg(gin + s2*32 + lane);
            a3 += __ldg(gin + s3*32 + lane);
        }
        for (; j < m; j++) {
            int s = __shfl_sync(0xffffffffu, idx, j);
            a0 += __ldg(gin + s*32 + lane);
        }
    }
    float val = fmaxf(dinv*((a0+a1)+(a2+a3)) + bias[lane], 0.f);
    if (MODE == 1) {
        float acc = 0.f;
        #pragma unroll
        for (int k = 0; k < 32; k++)
            acc += __shfl_sync(0xffffffffu, val, k) * W2s[k*G2 + lane];
        g_hs2[v*32 + lane] = acc * dinv;
    } else {
        g_h2[v*32 + lane] = val;
        float p   = pw[lane];
        float nrm = p*p;
        float dot = val*p;
        #pragma unroll
        for (int o = 16; o; o >>= 1) {
            nrm += __shfl_xor_sync(0xffffffffu, nrm, o);
            dot += __shfl_xor_sync(0xffffffffu, dot, o);
        }
        if (lane == 0) g_score[v] = tanhf(dot * rsqrtf(nrm));
    }
}

// ---------------- top-k pool + dense head (one CTA per batch) ----------------
__global__ void k_topk(const float* __restrict__ dense_W, const float* __restrict__ dense_b,
                       const float* __restrict__ out_W,  const float* __restrict__ out_b,
                       float* __restrict__ out) {
    __shared__ float ss[2048];
    __shared__ float red[32*32];
    __shared__ float gvec[G2];
    __shared__ float dvec[DENSE];
    int b = blockIdx.x, tid = threadIdx.x;
    for (int i = tid; i < 2048; i += 1024)
        ss[i] = (i < NGPB) ? g_score[b*NGPB + i] : -FLT_MAX;
    __syncthreads();
    // bitonic ascending sort of 2048 elements
    for (int k = 2; k <= 2048; k <<= 1)
        for (int j = k >> 1; j > 0; j >>= 1) {
            for (int i = tid; i < 2048; i += 1024) {
                int ixj = i ^ j;
                if (ixj > i) {
                    float a = ss[i], c = ss[ixj];
                    bool up = ((i & k) == 0);
                    if ((a > c) == up) { ss[i] = c; ss[ixj] = a; }
                }
            }
            __syncthreads();
        }
    float thr = ss[2048 - KSEL];   // K-th largest score
    // feature-wise max over selected nodes of h2[i]*score[i]
    int warp = tid >> 5, lane = tid & 31;
    float m = -FLT_MAX;
    for (int i = warp; i < NGPB; i += 32) {
        int v = b*NGPB + i;
        float sc = g_score[v];
        if (sc >= thr) m = fmaxf(m, g_h2[v*32 + lane] * sc);
    }
    red[warp*32 + lane] = m;
    __syncthreads();
    if (tid < G2) {
        float mm = -FLT_MAX;
        #pragma unroll
        for (int w = 0; w < 32; w++) mm = fmaxf(mm, red[w*32 + tid]);
        gvec[tid] = mm;
    }
    __syncthreads();
    if (tid < DENSE) {
        float acc = dense_b[tid];
        #pragma unroll
        for (int k = 0; k < G2; k++) acc += gvec[k]*dense_W[k*DENSE + tid];
        dvec[tid] = fmaxf(acc, 0.f);
    }
    __syncthreads();
    if (tid < NCLS) {
        float acc = out_b[tid];
        #pragma unroll
        for (int k = 0; k < DENSE; k++) acc += dvec[k]*out_W[k*NCLS + tid];
        out[b*NCLS + tid] = acc;
    }
}

// ---------------- launch -----------------------------------------------------
extern "C" void kernel_launch(void* const* d_in, const int* in_sizes, int n_in,
                              void* d_out, int out_size) {
    const int*   x   = (const int*)  d_in[0];
    const int*   ei  = (const int*)  d_in[1];
    // d_in[2] = batch (implicit in layout, unused)
    const float* emb = (const float*)d_in[3];
    const float* W1  = (const float*)d_in[4];
    const float* b1  = (const float*)d_in[5];
    const float* W2  = (const float*)d_in[6];
    const float* b2  = (const float*)d_in[7];
    const float* pw  = (const float*)d_in[8];
    const float* dW  = (const float*)d_in[9];
    const float* db  = (const float*)d_in[10];
    const float* oW  = (const float*)d_in[11];
    const float* ob  = (const float*)d_in[12];
    float* out = (float*)d_out;

    k_embW1 <<<FEAT/8, 256>>>(emb, W1);
    k_build <<<NB*2, 1024>>>(ei, x);
    k_agg<1><<<NN/16, 512>>>(b1, W2, pw);
    k_agg<2><<<NN/16, 512>>>(b2, W2, pw);
    k_topk  <<<NB, 1024>>>(dW, db, oW, ob, out);
}

// round 4
// speedup vs baseline: 1.9717x; 1.1326x over previous
#include <cuda_runtime.h>
#include <math.h>
#include <float.h>

#define NB    64
#define NGPB  2000
#define EGPB  64000
#define NN    (NB*NGPB)     // 128000 nodes
#define NE    (NB*EGPB)     // 4096000 edges
#define KSEL  1600
#define EMB   64
#define G1    32
#define G2    32
#define DENSE 64
#define NCLS  10
#define FEAT  10000
#define CAP   96            // padded CSR bucket capacity (deg mean 32, max ~62)
#define QTR   500           // dst nodes owned per build-CTA (4 CTAs per batch)

// ---------------- scratch (static device globals; no runtime alloc) ----------
__device__ int   g_cnt[NN];             // per-node in-degree
__device__ float g_dinv[NN];
__device__ int   g_csrc[NN*CAP];        // padded CSR; pad entries = NN (zero row)
__device__ float g_embW1[FEAT*G1];      // emb @ W1  (10000 x 32)
__device__ float g_hs [(NN+1)*G1];      // layer-1 input (pre-scaled); row NN = zeros
__device__ float g_hs2[(NN+1)*G2];      // layer-2 input (pre-scaled); row NN = zeros
__device__ float g_h2 [NN*G2];          // final node features
__device__ float g_score[NN];

// ---------------- emb @ W1 (tiny table GEMM) + zero-row init -----------------
__global__ void k_embW1(const float* __restrict__ emb, const float* __restrict__ W1) {
    __shared__ float W1s[EMB*G1];
    for (int i = threadIdx.x; i < EMB*G1; i += blockDim.x) W1s[i] = W1[i];
    __syncthreads();
    if (blockIdx.x == 0 && threadIdx.x < 32) {   // zero pad rows once per launch
        g_hs [NN*G1 + threadIdx.x] = 0.f;
        g_hs2[NN*G2 + threadIdx.x] = 0.f;
    }
    int warp = threadIdx.x >> 5, lane = threadIdx.x & 31;
    int r = blockIdx.x*8 + warp;
    if (r >= FEAT) return;
    float e0 = emb[r*EMB + lane];
    float e1 = emb[r*EMB + 32 + lane];
    float acc = 0.f;
    #pragma unroll
    for (int k = 0; k < 32; k++)
        acc += __shfl_sync(0xffffffffu, e0, k) * W1s[k*G1 + lane];
    #pragma unroll
    for (int k = 0; k < 32; k++)
        acc += __shfl_sync(0xffffffffu, e1, k) * W1s[(32+k)*G1 + lane];
    g_embW1[r*G1 + lane] = acc;
}

// ---------------- fused CSR build (SMEM-staged) + dinv + hs ------------------
// 4 CTAs per batch; CTA owns dst range [b*NGPB + q*QTR, +QTR).
// Buckets staged in SMEM (pre-filled with NN = zero-row pad), written out
// coalesced as int4. Edges of batch b are contiguous in the edge list.
__global__ void __launch_bounds__(1024) k_build(const int* __restrict__ ei,
                                                const int* __restrict__ x) {
    extern __shared__ int sm[];          // [0,QTR): scnt ; [QTR, QTR+QTR*CAP): buckets
    int* scnt  = sm;
    int* sbuck = sm + QTR;
    int b = blockIdx.x >> 2, q = blockIdx.x & 3;
    int tid = threadIdx.x;
    for (int i = tid; i < QTR; i += 1024) scnt[i] = 0;
    for (int i = tid; i < QTR*CAP; i += 1024) sbuck[i] = NN;   // pad = zero row
    __syncthreads();
    int ebase = b*EGPB;
    int lo    = b*NGPB + q*QTR;
    const int*  __restrict__ srcs = ei + ebase;
    const int4* __restrict__ d4   = (const int4*)(ei + NE + ebase);
    for (int t = tid; t < EGPB/4; t += 1024) {
        int4 d = d4[t];
        int j = t*4;
        unsigned r;
        r = (unsigned)(d.x - lo);
        if (r < QTR) sbuck[r*CAP + atomicAdd(&scnt[r], 1)] = srcs[j+0];
        r = (unsigned)(d.y - lo);
        if (r < QTR) sbuck[r*CAP + atomicAdd(&scnt[r], 1)] = srcs[j+1];
        r = (unsigned)(d.z - lo);
        if (r < QTR) sbuck[r*CAP + atomicAdd(&scnt[r], 1)] = srcs[j+2];
        r = (unsigned)(d.w - lo);
        if (r < QTR) sbuck[r*CAP + atomicAdd(&scnt[r], 1)] = srcs[j+3];
    }
    __syncthreads();
    // coalesced bucket writeout
    int4* __restrict__ out4 = (int4*)(g_csrc + lo*CAP);
    const int4* __restrict__ sb4 = (const int4*)sbuck;
    for (int i = tid; i < QTR*CAP/4; i += 1024) out4[i] = sb4[i];
    // cnt, dinv, hs for owned nodes (warp per node)
    int warp = tid >> 5, lane = tid & 31;
    for (int i = warp; i < QTR; i += 32) {
        int v = lo + i;
        int c = scnt[i];
        float dinv = rsqrtf((float)(c + 1));      // +1 self loop
        if (lane == 0) { g_cnt[v] = c; g_dinv[v] = dinv; }
        int row = x[v];
        g_hs[v*32 + lane] = g_embW1[row*32 + lane] * dinv;
    }
}

// ---------------- GCN aggregation (8-lane group per dst node) ----------------
// Lane g in [0,8) of each group owns features [g*4, g*4+4) as float4.
// out[v] = relu(dinv[v] * (self + sum_{u->v} gin[u]) + bias)
// MODE 1: fuse @W2, scale by dinv -> g_hs2.  MODE 2: write h2 + pooling score.
template<int MODE>
__global__ void __launch_bounds__(512) k_agg(const float* __restrict__ bias,
                                             const float* __restrict__ W2,
                                             const float* __restrict__ pw) {
    __shared__ float W2s[G2*G2];
    if (MODE == 1) {
        for (int i = threadIdx.x; i < G2*G2; i += blockDim.x) W2s[i] = W2[i];
        __syncthreads();
    }
    const float4* __restrict__ gin4 =
        (const float4*)((MODE == 1) ? g_hs : g_hs2);   // row = 8 float4s
    int lane = threadIdx.x & 31;
    int g    = lane & 7;                 // lane within group
    int wid  = blockIdx.x*(blockDim.x >> 5) + (threadIdx.x >> 5);
    int v    = wid*4 + (lane >> 3);      // node for this group (grid exact: v < NN)
    int dg        = g_cnt[v];
    float dinv    = g_dinv[v];
    const int* __restrict__ bucket = g_csrc + v*CAP;

    float4 a0 = __ldg(gin4 + v*8 + g);   // self loop
    float4 a1 = make_float4(0.f, 0.f, 0.f, 0.f);
    for (int j = 0; j < dg; j += 4) {    // pad entries index the zero row
        int4 i4 = *(const int4*)(bucket + j);
        float4 v0 = __ldg(gin4 + i4.x*8 + g);
        float4 v1 = __ldg(gin4 + i4.y*8 + g);
        float4 v2 = __ldg(gin4 + i4.z*8 + g);
        float4 v3 = __ldg(gin4 + i4.w*8 + g);
        a0.x += v0.x; a0.y += v0.y; a0.z += v0.z; a0.w += v0.w;
        a1.x += v1.x; a1.y += v1.y; a1.z += v1.z; a1.w += v1.w;
        a0.x += v2.x; a0.y += v2.y; a0.z += v2.z; a0.w += v2.w;
        a1.x += v3.x; a1.y += v3.y; a1.z += v3.z; a1.w += v3.w;
    }
    float4 bias4 = *(const float4*)(bias + g*4);
    float4 val;
    val.x = fmaxf(dinv*(a0.x + a1.x) + bias4.x, 0.f);
    val.y = fmaxf(dinv*(a0.y + a1.y) + bias4.y, 0.f);
    val.z = fmaxf(dinv*(a0.z + a1.z) + bias4.z, 0.f);
    val.w = fmaxf(dinv*(a0.w + a1.w) + bias4.w, 0.f);

    if (MODE == 1) {
        // hs2[v][c] = dinv * sum_k val_k W2[k][c], c = g*4..g*4+3
        float4 acc = make_float4(0.f, 0.f, 0.f, 0.f);
        int base = lane & ~7;
        #pragma unroll
        for (int k8 = 0; k8 < 8; k8++) {
            float vx = __shfl_sync(0xffffffffu, val.x, base + k8);
            float vy = __shfl_sync(0xffffffffu, val.y, base + k8);
            float vz = __shfl_sync(0xffffffffu, val.z, base + k8);
            float vw = __shfl_sync(0xffffffffu, val.w, base + k8);
            float4 w0 = *(const float4*)&W2s[(k8*4+0)*G2 + g*4];
            float4 w1 = *(const float4*)&W2s[(k8*4+1)*G2 + g*4];
            float4 w2 = *(const float4*)&W2s[(k8*4+2)*G2 + g*4];
            float4 w3 = *(const float4*)&W2s[(k8*4+3)*G2 + g*4];
            acc.x += vx*w0.x + vy*w1.x + vz*w2.x + vw*w3.x;
            acc.y += vx*w0.y + vy*w1.y + vz*w2.y + vw*w3.y;
            acc.z += vx*w0.z + vy*w1.z + vz*w2.z + vw*w3.z;
            acc.w += vx*w0.w + vy*w1.w + vz*w2.w + vw*w3.w;
        }
        float4 o;
        o.x = acc.x*dinv; o.y = acc.y*dinv; o.z = acc.z*dinv; o.w = acc.w*dinv;
        *(float4*)((float*)g_hs2 + v*32 + g*4) = o;
    } else {
        *(float4*)(g_h2 + v*32 + g*4) = val;
        float4 p = *(const float4*)(pw + g*4);
        float dot = val.x*p.x + val.y*p.y + val.z*p.z + val.w*p.w;
        float nrm = p.x*p.x + p.y*p.y + p.z*p.z + p.w*p.w;
        #pragma unroll
        for (int o = 1; o < 8; o <<= 1) {      // reduce within 8-lane group
            dot += __shfl_xor_sync(0xffffffffu, dot, o);
            nrm += __shfl_xor_sync(0xffffffffu, nrm, o);
        }
        if (g == 0) g_score[v] = tanhf(dot * rsqrtf(nrm));
    }
}

// ---------------- top-k pool + dense head (one CTA per batch) ----------------
__global__ void k_topk(const float* __restrict__ dense_W, const float* __restrict__ dense_b,
                       const float* __restrict__ out_W,  const float* __restrict__ out_b,
                       float* __restrict__ out) {
    __shared__ float ss[2048];
    __shared__ float red[32*32];
    __shared__ float gvec[G2];
    __shared__ float dvec[DENSE];
    int b = blockIdx.x, tid = threadIdx.x;
    for (int i = tid; i < 2048; i += 1024)
        ss[i] = (i < NGPB) ? g_score[b*NGPB + i] : -FLT_MAX;
    __syncthreads();
    // bitonic ascending sort of 2048 elements
    for (int k = 2; k <= 2048; k <<= 1)
        for (int j = k >> 1; j > 0; j >>= 1) {
            for (int i = tid; i < 2048; i += 1024) {
                int ixj = i ^ j;
                if (ixj > i) {
                    float a = ss[i], c = ss[ixj];
                    bool up = ((i & k) == 0);
                    if ((a > c) == up) { ss[i] = c; ss[ixj] = a; }
                }
            }
            __syncthreads();
        }
    float thr = ss[2048 - KSEL];   // K-th largest score
    // feature-wise max over selected nodes of h2[i]*score[i]
    int warp = tid >> 5, lane = tid & 31;
    float m = -FLT_MAX;
    for (int i = warp; i < NGPB; i += 32) {
        int v = b*NGPB + i;
        float sc = g_score[v];
        if (sc >= thr) m = fmaxf(m, g_h2[v*32 + lane] * sc);
    }
    red[warp*32 + lane] = m;
    __syncthreads();
    if (tid < G2) {
        float mm = -FLT_MAX;
        #pragma unroll
        for (int w = 0; w < 32; w++) mm = fmaxf(mm, red[w*32 + tid]);
        gvec[tid] = mm;
    }
    __syncthreads();
    if (tid < DENSE) {
        float acc = dense_b[tid];
        #pragma unroll
        for (int k = 0; k < G2; k++) acc += gvec[k]*dense_W[k*DENSE + tid];
        dvec[tid] = fmaxf(acc, 0.f);
    }
    __syncthreads();
    if (tid < NCLS) {
        float acc = out_b[tid];
        #pragma unroll
        for (int k = 0; k < DENSE; k++) acc += dvec[k]*out_W[k*NCLS + tid];
        out[b*NCLS + tid] = acc;
    }
}

// ---------------- launch -----------------------------------------------------
extern "C" void kernel_launch(void* const* d_in, const int* in_sizes, int n_in,
                              void* d_out, int out_size) {
    const int*   x   = (const int*)  d_in[0];
    const int*   ei  = (const int*)  d_in[1];
    // d_in[2] = batch (implicit in layout, unused)
    const float* emb = (const float*)d_in[3];
    const float* W1  = (const float*)d_in[4];
    const float* b1  = (const float*)d_in[5];
    const float* W2  = (const float*)d_in[6];
    const float* b2  = (const float*)d_in[7];
    const float* pw  = (const float*)d_in[8];
    const float* dW  = (const float*)d_in[9];
    const float* db  = (const float*)d_in[10];
    const float* oW  = (const float*)d_in[11];
    const float* ob  = (const float*)d_in[12];
    float* out = (float*)d_out;

    static int smem_set = 0;
    const int BUILD_SMEM = (QTR + QTR*CAP) * (int)sizeof(int);  // 194 000 B
    if (!smem_set) {
        cudaFuncSetAttribute(k_build, cudaFuncAttributeMaxDynamicSharedMemorySize,
                             BUILD_SMEM);
        smem_set = 1;
    }

    k_embW1 <<<FEAT/8, 256>>>(emb, W1);
    k_build <<<NB*4, 1024, BUILD_SMEM>>>(ei, x);
    k_agg<1><<<NN/64, 512>>>(b1, W2, pw);
    k_agg<2><<<NN/64, 512>>>(b2, W2, pw);
    k_topk  <<<NB, 1024>>>(dW, db, oW, ob, out);
}